// round 12
// baseline (speedup 1.0000x reference)
#include <cuda_runtime.h>
#include <cuda_fp16.h>
#include <math.h>
#include <stdint.h>

#define NPTS 16384
#define KNB  32
#define PKP  15
#define CIN  256
#define CMID 128
#define COUT 512
#define PC   (PKP * CMID)   // 1920

typedef unsigned long long ull;
typedef __half f16;

// ---------------------------------------------------------------------------
// Scratch (device globals -- allocation-free)
// ---------------------------------------------------------------------------
__device__ __align__(128) f16   g_xs  [2ull * NPTS * CIN];                  // fp16
__device__ __align__(128) f16   g_h   [2ull * NPTS * CMID];                 // fp16
__device__ __align__(128) f16   g_ag  [2ull * NPTS * PC];                   // fp16
__device__ __align__(128) f16   g_md  [2ull * NPTS * CMID];                 // fp16
__device__ __align__(128) f16   g_y   [2ull * NPTS * COUT];                 // fp16
__device__ __align__(128) f16   g_wi_h[CIN * CMID],  g_wi_l[CIN * CMID];    // split
__device__ __align__(128) f16   g_kw  [PC * CMID];                          // single
__device__ __align__(128) f16   g_wo_h[CMID * COUT], g_wo_l[CMID * COUT];   // split
__device__ float g_stats[2 * 2 * COUT];

// ---------------------------------------------------------------------------
// PTX helpers
// ---------------------------------------------------------------------------
__device__ __forceinline__ uint32_t s2u(const void* p)
{
    return (uint32_t)__cvta_generic_to_shared(p);
}
__device__ __forceinline__ void cpa16(uint32_t s, const void* g)
{
    asm volatile("cp.async.cg.shared.global [%0], [%1], 16;" :: "r"(s), "l"(g));
}
__device__ __forceinline__ void cp_commit()
{
    asm volatile("cp.async.commit_group;" ::: "memory");
}
template <int N>
__device__ __forceinline__ void cp_wait()
{
    asm volatile("cp.async.wait_group %0;" :: "n"(N) : "memory");
}
__device__ __forceinline__ void ldsm4(uint32_t* r, uint32_t a)
{
    asm volatile("ldmatrix.sync.aligned.m8n8.x4.shared.b16 {%0,%1,%2,%3}, [%4];"
                 : "=r"(r[0]), "=r"(r[1]), "=r"(r[2]), "=r"(r[3]) : "r"(a));
}
__device__ __forceinline__ void ldsm4t(uint32_t* r, uint32_t a)
{
    asm volatile("ldmatrix.sync.aligned.m8n8.x4.trans.shared.b16 {%0,%1,%2,%3}, [%4];"
                 : "=r"(r[0]), "=r"(r[1]), "=r"(r[2]), "=r"(r[3]) : "r"(a));
}
__device__ __forceinline__ void mma_hf(float* c, const uint32_t* a, const uint32_t* b)
{
    asm volatile(
        "mma.sync.aligned.m16n8k16.row.col.f32.f16.f16.f32 "
        "{%0,%1,%2,%3}, {%4,%5,%6,%7}, {%8,%9}, {%0,%1,%2,%3};"
        : "+f"(c[0]), "+f"(c[1]), "+f"(c[2]), "+f"(c[3])
        : "r"(a[0]), "r"(a[1]), "r"(a[2]), "r"(a[3]), "r"(b[0]), "r"(b[1]));
}
__device__ __forceinline__ void fma2(ull& d, ull a, ull b)
{
    asm("fma.rn.f32x2 %0, %1, %2, %0;" : "+l"(d) : "l"(a), "l"(b));
}
__device__ __forceinline__ ull pack2(float x, float y)
{
    ull r;
    asm("mov.b64 %0, {%1, %2};" : "=l"(r) : "f"(x), "f"(y));
    return r;
}
__device__ __forceinline__ void unpack2(ull v, float& x, float& y)
{
    asm("mov.b64 {%0, %1}, %2;" : "=f"(x), "=f"(y) : "l"(v));
}

// ---------------------------------------------------------------------------
// Unified fp16 HMMA GEMM. A fp16 single; B fp16 single (BSPLIT=0) or hi/lo
// split (BSPLIT=1, 2 MMAs). CTA tile 128x128, BK=64, 8 warps (2m x 4n),
// warp tile 64x32. 3-stage cp.async pipeline. Stage: A[16K] + B[16K or 32K].
// OUT 0: fp16 out (+bias if non-null).
// OUT 1: fp16 out (+bias) AND per-channel BN stats (fp32, pre-quantization).
// blockIdx = (nTile, mTile, branch)
// ---------------------------------------------------------------------------
template <int BSPLIT>
__device__ __forceinline__ void issue_hg(
    const f16* gA, const f16* gBh, const f16* gBl,
    int K, int Ntot, int c, uint32_t sb, int tid)
{
    const int kt = c * 64;
#pragma unroll
    for (int i = 0; i < 4; i++) {
        int idx = tid + i * 256;            // A: 128 rows x 8 16B-chunks
        int r = idx >> 3, ch = idx & 7;
        uint32_t off = (uint32_t)(r * 128 + ((ch ^ (r & 7)) << 4));
        cpa16(sb + off, gA + (size_t)r * K + kt + ch * 8);
    }
#pragma unroll
    for (int i = 0; i < 4; i++) {
        int idx = tid + i * 256;            // B: 64 rows x 16 16B-chunks
        int r = idx >> 4, ch = idx & 15;
        uint32_t off = (uint32_t)(r * 256 + ((ch ^ (r & 7)) << 4));
        size_t go = (size_t)(kt + r) * Ntot + ch * 8;
        cpa16(sb + 16384 + off, gBh + go);
        if (BSPLIT) cpa16(sb + 32768 + off, gBl + go);
    }
    cp_commit();
}

template <int BSPLIT, int OUT>
__global__ void __launch_bounds__(256)
hgemm(const f16* __restrict__ A, const f16* __restrict__ Bh,
      const f16* __restrict__ Bl, const float* __restrict__ bias,
      f16* __restrict__ Cs, float* __restrict__ stats,
      int K, int Ntot)
{
    constexpr int STAGE = 16384 + (BSPLIT ? 32768 : 16384);
    extern __shared__ char smem[];
    const uint32_t sb0 = s2u(smem);

    const int tid  = threadIdx.x;
    const int wid  = tid >> 5;
    const int lane = tid & 31;
    const int z     = blockIdx.z;
    const int mTile = blockIdx.y;
    const int nTile = blockIdx.x;

    const int m0 = (wid & 1) * 64;
    const int n0 = (wid >> 1) * 32;

    const size_t brA = (size_t)z * NPTS * K;
    const size_t brC = (size_t)z * NPTS * Ntot;
    const f16* gA  = A + brA + (size_t)mTile * 128 * K;
    const f16* gBh = Bh + (size_t)nTile * 128;
    const f16* gBl = BSPLIT ? Bl + (size_t)nTile * 128 : nullptr;

    float acc[4][4][4];
#pragma unroll
    for (int i = 0; i < 4; i++)
#pragma unroll
        for (int j = 0; j < 4; j++)
#pragma unroll
            for (int t = 0; t < 4; t++) acc[i][j][t] = 0.0f;

    const int nch = K >> 6;
    issue_hg<BSPLIT>(gA, gBh, gBl, K, Ntot, 0, sb0, tid);
    if (nch > 1)
        issue_hg<BSPLIT>(gA, gBh, gBl, K, Ntot, 1, sb0 + STAGE, tid);
    else
        cp_commit();

    int bufn = 2 % 3;
    for (int c = 0; c < nch; c++) {
        if (c + 2 < nch)
            issue_hg<BSPLIT>(gA, gBh, gBl, K, Ntot, c + 2,
                             sb0 + bufn * STAGE, tid);
        else
            cp_commit();
        bufn = bufn == 2 ? 0 : bufn + 1;
        cp_wait<2>();
        __syncthreads();

        const uint32_t sb = sb0 + (c % 3) * STAGE;
        const uint32_t sA = sb, sB = sb + 16384;

#pragma unroll
        for (int ks = 0; ks < 4; ks++) {
            uint32_t bh[4][2], bl[4][2];
#pragma unroll
            for (int pr = 0; pr < 2; pr++) {
                int k   = ks * 16 + (lane & 15);
                int chn = ((n0 + pr * 16) >> 3) + (lane >> 4);
                uint32_t ba = sB + (uint32_t)(k * 256 + ((chn ^ (k & 7)) << 4));
                uint32_t t[4];
                ldsm4t(t, ba);
                bh[pr * 2][0] = t[0]; bh[pr * 2][1] = t[1];
                bh[pr * 2 + 1][0] = t[2]; bh[pr * 2 + 1][1] = t[3];
                if (BSPLIT) {
                    ldsm4t(t, ba + 16384);
                    bl[pr * 2][0] = t[0]; bl[pr * 2][1] = t[1];
                    bl[pr * 2 + 1][0] = t[2]; bl[pr * 2 + 1][1] = t[3];
                }
            }
#pragma unroll
            for (int mf = 0; mf < 4; mf++) {
                int r   = m0 + mf * 16 + (lane & 15);
                int chk = ks * 2 + (lane >> 4);
                uint32_t aa = sA + (uint32_t)(r * 128 + ((chk ^ (r & 7)) << 4));
                uint32_t av[4];
                ldsm4(av, aa);
#pragma unroll
                for (int nf = 0; nf < 4; nf++) {
                    mma_hf(acc[mf][nf], av, bh[nf]);
                    if (BSPLIT) mma_hf(acc[mf][nf], av, bl[nf]);
                }
            }
        }
        __syncthreads();
    }

    const int g  = lane >> 2;
    const int tg = lane & 3;

    float ts[4][2], tq[4][2];
    if (OUT == 1) {
#pragma unroll
        for (int nf = 0; nf < 4; nf++)
            ts[nf][0] = ts[nf][1] = tq[nf][0] = tq[nf][1] = 0.0f;
    }

#pragma unroll
    for (int mf = 0; mf < 4; mf++) {
#pragma unroll
        for (int nf = 0; nf < 4; nf++) {
            int col = nTile * 128 + n0 + nf * 8 + tg * 2;
            float b0 = bias ? bias[col] : 0.0f;
            float b1 = bias ? bias[col + 1] : 0.0f;
#pragma unroll
            for (int hrow = 0; hrow < 2; hrow++) {
                int row = mTile * 128 + m0 + mf * 16 + g + hrow * 8;
                float v0 = acc[mf][nf][hrow * 2 + 0] + b0;
                float v1 = acc[mf][nf][hrow * 2 + 1] + b1;
                size_t o = brC + (size_t)row * Ntot + col;
                __half2 p = __floats2half2_rn(v0, v1);
                *reinterpret_cast<__half2*>(Cs + o) = p;
                if (OUT == 1) {
                    ts[nf][0] += v0;  tq[nf][0] = fmaf(v0, v0, tq[nf][0]);
                    ts[nf][1] += v1;  tq[nf][1] = fmaf(v1, v1, tq[nf][1]);
                }
            }
        }
    }

    if (OUT == 1) {
        float* st = stats + (size_t)z * 2 * COUT;
#pragma unroll
        for (int nf = 0; nf < 4; nf++) {
#pragma unroll
            for (int p = 0; p < 2; p++) {
#pragma unroll
                for (int off = 4; off <= 16; off <<= 1) {
                    ts[nf][p] += __shfl_xor_sync(0xFFFFFFFFu, ts[nf][p], off);
                    tq[nf][p] += __shfl_xor_sync(0xFFFFFFFFu, tq[nf][p], off);
                }
            }
        }
        if (lane < 4) {
#pragma unroll
            for (int nf = 0; nf < 4; nf++) {
                int col = nTile * 128 + n0 + nf * 8 + tg * 2;
                atomicAdd(&st[col],            ts[nf][0]);
                atomicAdd(&st[col + 1],        ts[nf][1]);
                atomicAdd(&st[COUT + col],     tq[nf][0]);
                atomicAdd(&st[COUT + col + 1], tq[nf][1]);
            }
        }
    }
}

// ---------------------------------------------------------------------------
// Conversions
// ---------------------------------------------------------------------------
__global__ void __launch_bounds__(256)
conv_act_f16(const float* __restrict__ a0, const float* __restrict__ a1,
             f16* __restrict__ o, int n4)
{
    const int z = blockIdx.y;
    const float* a = z ? a1 : a0;
    const size_t off = (size_t)z * n4;
    int i = blockIdx.x * 256 + threadIdx.x;
    if (i < n4) {
        float4 v = reinterpret_cast<const float4*>(a)[i];
        __half2 p0 = __floats2half2_rn(v.x, v.y);
        __half2 p1 = __floats2half2_rn(v.z, v.w);
        uint2 pk;
        pk.x = *reinterpret_cast<uint32_t*>(&p0);
        pk.y = *reinterpret_cast<uint32_t*>(&p1);
        reinterpret_cast<uint2*>(o)[off + i] = pk;
    }
}

__global__ void __launch_bounds__(256)
split_w_f16(const float* __restrict__ in, f16* __restrict__ oh, f16* __restrict__ ol, int n)
{
    int i = blockIdx.x * 256 + threadIdx.x;
    if (i < n) {
        float v = in[i];
        f16 h = __float2half(v);
        oh[i] = h;
        if (ol) ol[i] = __float2half(v - __half2float(h));
    }
}

// ---------------------------------------------------------------------------
// KPConv aggregation, f32x2 packed-FMA, 4 channels/thread.
// 128-thread CTA = 4 points; thread u in [0,32) of each point handles
// channels 4u..4u+3. Inner loop per (k,p): 1 LDS.64 + 2 FFMA2
// (LDS amortized over 2 packed FMAs -> FMA-pipe-bound).
// ---------------------------------------------------------------------------
__global__ void __launch_bounds__(128)
kpconv_agg4(const f16* __restrict__ hbuf,
            const float* __restrict__ coords0, const float* __restrict__ coords1,
            const int* __restrict__ neighb0, const int* __restrict__ neighb1,
            const float* __restrict__ kpts, f16* __restrict__ agg)
{
    const int z = blockIdx.z;
    const float* coords = z ? coords1 : coords0;
    const int*   neighb = z ? neighb1 : neighb0;
    const size_t brH = (size_t)z * NPTS * CMID;
    const size_t brA = (size_t)z * NPTS * PC;

    const int t   = threadIdx.x;
    const int pt  = t >> 5;              // 0..3: point within CTA
    const int u   = t & 31;              // channel-quad index (4 channels)
    const int n   = blockIdx.x * 4 + pt;

    __shared__ int   nb_s[4][KNB];
    __shared__ float rel_s[4][KNB][3];
    __shared__ __align__(8) ull ipack[4][KNB][16];   // {infl,infl} packed

    nb_s[pt][u] = neighb[n * KNB + u];
    __syncthreads();
    for (int idx = u; idx < KNB * 3; idx += 32) {
        int k = idx / 3, d = idx % 3;
        rel_s[pt][k][d] = coords[(size_t)nb_s[pt][k] * 3 + d]
                        - coords[(size_t)n * 3 + d];
    }
    __syncthreads();
    for (int idx = u; idx < KNB * PKP; idx += 32) {
        int k = idx / PKP, p = idx % PKP;
        float dx = rel_s[pt][k][0] - kpts[p * 3 + 0];
        float dy = rel_s[pt][k][1] - kpts[p * 3 + 1];
        float dz = rel_s[pt][k][2] - kpts[p * 3 + 2];
        float d  = sqrtf(dx * dx + dy * dy + dz * dz);
        float iv = fmaxf(0.0f, 1.0f - d * 1.25f);   // EXTENT = 0.8
        ipack[pt][k][p] = pack2(iv, iv);
    }
    __syncthreads();

    ull acc2[PKP][2];
#pragma unroll
    for (int p = 0; p < PKP; p++) { acc2[p][0] = 0ull; acc2[p][1] = 0ull; }

#pragma unroll 2
    for (int k = 0; k < KNB; k++) {
        // one 8B gather: channels 4u..4u+3 of neighbor k
        uint2 hv = __ldg(reinterpret_cast<const uint2*>(
            hbuf + brH + (size_t)nb_s[pt][k] * CMID + u * 4));
        __half2 h01 = *reinterpret_cast<__half2*>(&hv.x);
        __half2 h23 = *reinterpret_cast<__half2*>(&hv.y);
        float2 f01 = __half22float2(h01);
        float2 f23 = __half22float2(h23);
        ull av0 = pack2(f01.x, f01.y);
        ull av1 = pack2(f23.x, f23.y);
        const ull* ip = ipack[pt][k];
#pragma unroll
        for (int p = 0; p < PKP; p++) {
            ull iv = ip[p];
            fma2(acc2[p][0], av0, iv);
            fma2(acc2[p][1], av1, iv);
        }
    }

    f16* o = agg + brA + (size_t)n * PC + u * 4;
#pragma unroll
    for (int p = 0; p < PKP; p++) {
        float x0, y0, x1, y1;
        unpack2(acc2[p][0], x0, y0);
        unpack2(acc2[p][1], x1, y1);
        __half2 h01 = __floats2half2_rn(x0, y0);
        __half2 h23 = __floats2half2_rn(x1, y1);
        uint2 pk;
        pk.x = *reinterpret_cast<uint32_t*>(&h01);
        pk.y = *reinterpret_cast<uint32_t*>(&h23);
        *reinterpret_cast<uint2*>(o + (size_t)p * CMID) = pk;
    }
}

// ---------------------------------------------------------------------------
// BatchNorm apply (y fp16, stats fp32 from GEMM3 epilogue)
// ---------------------------------------------------------------------------
__global__ void zero_stats(float* s)
{
    s[blockIdx.x * 1024 + threadIdx.x] = 0.0f;   // <<<2, 1024>>>
}

__global__ void __launch_bounds__(256)
bn_apply4(const f16* __restrict__ ybase, const float* __restrict__ stats,
          const float* __restrict__ gamma, const float* __restrict__ beta,
          float* __restrict__ outbase)
{
    const int z = blockIdx.y;
    const f16*   y   = ybase + (size_t)z * NPTS * COUT;
    const float* st  = stats + (size_t)z * 2 * COUT;
    float*       out = outbase + (size_t)z * NPTS * COUT;

    const int i = blockIdx.x * blockDim.x + threadIdx.x;   // quad index
    const int c = (i * 4) & (COUT - 1);
    uint2 pk = reinterpret_cast<const uint2*>(y)[i];
    __half2 h01 = *reinterpret_cast<__half2*>(&pk.x);
    __half2 h23 = *reinterpret_cast<__half2*>(&pk.y);
    float2 f01 = __half22float2(h01);
    float2 f23 = __half22float2(h23);
    float r[4] = {f01.x, f01.y, f23.x, f23.y};
#pragma unroll
    for (int j = 0; j < 4; j++) {
        float mu  = st[c + j] * (1.0f / NPTS);
        float var = st[COUT + c + j] * (1.0f / NPTS) - mu * mu;
        float scale = rsqrtf(var + 1e-5f) * gamma[c + j];
        float t = (r[j] - mu) * scale + beta[c + j];
        r[j] = (t >= 0.0f) ? t : 0.1f * t;
    }
    reinterpret_cast<float4*>(out)[i] = make_float4(r[0], r[1], r[2], r[3]);
}

__global__ void copy_coords(const float* __restrict__ a, const float* __restrict__ b,
                            float* __restrict__ out)
{
    int i = blockIdx.x * blockDim.x + threadIdx.x;
    if (i < NPTS * 3) {
        out[i]            = a[i];
        out[NPTS * 3 + i] = b[i];
    }
}

// ---------------------------------------------------------------------------
// Launcher
// ---------------------------------------------------------------------------
#define SMEM_SPLIT  (3 * 49152)
#define SMEM_SINGLE (3 * 32768)

extern "C" void kernel_launch(void* const* d_in, const int* in_sizes, int n_in,
                              void* d_out, int out_size)
{
    (void)in_sizes; (void)n_in; (void)out_size;

    const float* src    = (const float*)d_in[0];
    const float* tgt    = (const float*)d_in[1];
    const float* sc     = (const float*)d_in[2];
    const float* tc     = (const float*)d_in[3];
    const int*   snb    = (const int*)  d_in[4];
    const int*   tnb    = (const int*)  d_in[5];
    const float* W_in   = (const float*)d_in[6];
    const float* b_in   = (const float*)d_in[7];
    const float* kpts   = (const float*)d_in[8];
    const float* kpw    = (const float*)d_in[9];
    const float* W_out  = (const float*)d_in[10];
    const float* b_out  = (const float*)d_in[11];
    const float* gamma  = (const float*)d_in[12];
    const float* beta   = (const float*)d_in[13];
    float* out = (float*)d_out;

    f16 *xs, *h, *ag, *md, *y16, *wi_h, *wi_l, *kw, *wo_h, *wo_l;
    float *stats;
    cudaGetSymbolAddress((void**)&xs,   g_xs);
    cudaGetSymbolAddress((void**)&h,    g_h);
    cudaGetSymbolAddress((void**)&ag,   g_ag);
    cudaGetSymbolAddress((void**)&md,   g_md);
    cudaGetSymbolAddress((void**)&y16,  g_y);
    cudaGetSymbolAddress((void**)&wi_h, g_wi_h);  cudaGetSymbolAddress((void**)&wi_l, g_wi_l);
    cudaGetSymbolAddress((void**)&kw,   g_kw);
    cudaGetSymbolAddress((void**)&wo_h, g_wo_h);  cudaGetSymbolAddress((void**)&wo_l, g_wo_l);
    cudaGetSymbolAddress((void**)&stats, g_stats);

    cudaFuncSetAttribute((const void*)hgemm<1, 0>,
                         cudaFuncAttributeMaxDynamicSharedMemorySize, SMEM_SPLIT);
    cudaFuncSetAttribute((const void*)hgemm<0, 0>,
                         cudaFuncAttributeMaxDynamicSharedMemorySize, SMEM_SINGLE);
    cudaFuncSetAttribute((const void*)hgemm<1, 1>,
                         cudaFuncAttributeMaxDynamicSharedMemorySize, SMEM_SPLIT);

    // Weight preps
    split_w_f16<<<(CIN * CMID + 255) / 256, 256>>>(W_in, wi_h, wi_l, CIN * CMID);
    split_w_f16<<<(PC * CMID + 255) / 256, 256>>>(kpw, kw, nullptr, PC * CMID);
    split_w_f16<<<(CMID * COUT + 255) / 256, 256>>>(W_out, wo_h, wo_l, CMID * COUT);

    // Inputs -> fp16 (both branches)
    conv_act_f16<<<dim3((NPTS * CIN / 4 + 255) / 256, 2), 256>>>(
        src, tgt, xs, NPTS * CIN / 4);

    // Zero BN stats
    zero_stats<<<2, 1024>>>(stats);

    // GEMM1: h = x @ W_in + b_in (B split) -> fp16
    hgemm<1, 0><<<dim3(1, NPTS / 128, 2), 256, SMEM_SPLIT>>>(
        xs, wi_h, wi_l, b_in, h, nullptr, CIN, CMID);

    // KPConv gather + aggregation -> agg fp16
    kpconv_agg4<<<dim3(NPTS / 4, 1, 2), 128>>>(h, sc, tc, snb, tnb, kpts, ag);

    // mid = agg @ kpw (B single fp16, 1 MMA) -> fp16
    hgemm<0, 0><<<dim3(1, NPTS / 128, 2), 256, SMEM_SINGLE>>>(
        ag, kw, nullptr, nullptr, md, nullptr, PC, CMID);

    // y = mid @ W_out + b_out (B split) -> fp16 + fused BN stats (fp32)
    hgemm<1, 1><<<dim3(COUT / 128, NPTS / 128, 2), 256, SMEM_SPLIT>>>(
        md, wo_h, wo_l, b_out, y16, stats, CMID, COUT);

    // BN normalize + LeakyReLU
    bn_apply4<<<dim3((NPTS * COUT / 4) / 256, 2), 256>>>(y16, stats, gamma, beta, out);

    // coords pass-through
    copy_coords<<<(NPTS * 3 + 255) / 256, 256>>>(sc, tc, out + 2ull * NPTS * COUT);
}

// round 13
// speedup vs baseline: 1.0761x; 1.0761x over previous
#include <cuda_runtime.h>
#include <cuda_fp16.h>
#include <math.h>
#include <stdint.h>

#define NPTS 16384
#define KNB  32
#define PKP  15
#define CIN  256
#define CMID 128
#define COUT 512
#define PC   (PKP * CMID)   // 1920

typedef unsigned long long ull;
typedef __half f16;

// ---------------------------------------------------------------------------
// Scratch (device globals -- allocation-free)
// ---------------------------------------------------------------------------
__device__ __align__(128) f16   g_xs  [2ull * NPTS * CIN];
__device__ __align__(128) f16   g_h   [2ull * NPTS * CMID];
__device__ __align__(128) f16   g_ag  [2ull * NPTS * PC];
__device__ __align__(128) f16   g_md  [2ull * NPTS * CMID];
__device__ __align__(128) f16   g_y   [2ull * NPTS * COUT];
__device__ __align__(128) f16   g_wi_h[CIN * CMID],  g_wi_l[CIN * CMID];
__device__ __align__(128) f16   g_kw  [PC * CMID];
__device__ __align__(128) f16   g_wo_h[CMID * COUT], g_wo_l[CMID * COUT];
__device__ float g_stats[2 * 2 * COUT];

// ---------------------------------------------------------------------------
// PTX helpers
// ---------------------------------------------------------------------------
__device__ __forceinline__ uint32_t s2u(const void* p)
{
    return (uint32_t)__cvta_generic_to_shared(p);
}
__device__ __forceinline__ void cpa16(uint32_t s, const void* g)
{
    asm volatile("cp.async.cg.shared.global [%0], [%1], 16;" :: "r"(s), "l"(g));
}
__device__ __forceinline__ void cp_commit()
{
    asm volatile("cp.async.commit_group;" ::: "memory");
}
template <int N>
__device__ __forceinline__ void cp_wait()
{
    asm volatile("cp.async.wait_group %0;" :: "n"(N) : "memory");
}
__device__ __forceinline__ void ldsm4(uint32_t* r, uint32_t a)
{
    asm volatile("ldmatrix.sync.aligned.m8n8.x4.shared.b16 {%0,%1,%2,%3}, [%4];"
                 : "=r"(r[0]), "=r"(r[1]), "=r"(r[2]), "=r"(r[3]) : "r"(a));
}
__device__ __forceinline__ void ldsm4t(uint32_t* r, uint32_t a)
{
    asm volatile("ldmatrix.sync.aligned.m8n8.x4.trans.shared.b16 {%0,%1,%2,%3}, [%4];"
                 : "=r"(r[0]), "=r"(r[1]), "=r"(r[2]), "=r"(r[3]) : "r"(a));
}
__device__ __forceinline__ void mma_hf(float* c, const uint32_t* a, const uint32_t* b)
{
    asm volatile(
        "mma.sync.aligned.m16n8k16.row.col.f32.f16.f16.f32 "
        "{%0,%1,%2,%3}, {%4,%5,%6,%7}, {%8,%9}, {%0,%1,%2,%3};"
        : "+f"(c[0]), "+f"(c[1]), "+f"(c[2]), "+f"(c[3])
        : "r"(a[0]), "r"(a[1]), "r"(a[2]), "r"(a[3]), "r"(b[0]), "r"(b[1]));
}
__device__ __forceinline__ void fma2(ull& d, ull a, ull b)
{
    asm("fma.rn.f32x2 %0, %1, %2, %0;" : "+l"(d) : "l"(a), "l"(b));
}
__device__ __forceinline__ ull pack2(float x, float y)
{
    ull r;
    asm("mov.b64 %0, {%1, %2};" : "=l"(r) : "f"(x), "f"(y));
    return r;
}
__device__ __forceinline__ void unpack2(ull v, float& x, float& y)
{
    asm("mov.b64 {%0, %1}, %2;" : "=f"(x), "=f"(y) : "l"(v));
}

// ---------------------------------------------------------------------------
// Unified fp16 HMMA GEMM, templated pipeline depth.
// A fp16 single; B fp16 single (BSPLIT=0) or hi/lo split (BSPLIT=1, 2 MMAs).
// CTA tile 128x128, BK=64, 8 warps (2m x 4n), warp tile 64x32.
// Stage: A[16K] + B[16K or 32K]; NSTAGE stages (<=96KB total => 2 CTAs/SM).
// OUT 0: fp16 out (+bias). OUT 1: fp16 out (+bias) + fp32 BN stats.
// ---------------------------------------------------------------------------
template <int BSPLIT>
__device__ __forceinline__ void issue_hg(
    const f16* gA, const f16* gBh, const f16* gBl,
    int K, int Ntot, int c, uint32_t sb, int tid)
{
    const int kt = c * 64;
#pragma unroll
    for (int i = 0; i < 4; i++) {
        int idx = tid + i * 256;            // A: 128 rows x 8 16B-chunks
        int r = idx >> 3, ch = idx & 7;
        uint32_t off = (uint32_t)(r * 128 + ((ch ^ (r & 7)) << 4));
        cpa16(sb + off, gA + (size_t)r * K + kt + ch * 8);
    }
#pragma unroll
    for (int i = 0; i < 4; i++) {
        int idx = tid + i * 256;            // B: 64 rows x 16 16B-chunks
        int r = idx >> 4, ch = idx & 15;
        uint32_t off = (uint32_t)(r * 256 + ((ch ^ (r & 7)) << 4));
        size_t go = (size_t)(kt + r) * Ntot + ch * 8;
        cpa16(sb + 16384 + off, gBh + go);
        if (BSPLIT) cpa16(sb + 32768 + off, gBl + go);
    }
    cp_commit();
}

template <int BSPLIT, int OUT, int NSTAGE>
__global__ void __launch_bounds__(256)
hgemm(const f16* __restrict__ A, const f16* __restrict__ Bh,
      const f16* __restrict__ Bl, const float* __restrict__ bias,
      f16* __restrict__ Cs, float* __restrict__ stats,
      int K, int Ntot)
{
    constexpr int STAGE = 16384 + (BSPLIT ? 32768 : 16384);
    extern __shared__ char smem[];
    const uint32_t sb0 = s2u(smem);

    const int tid  = threadIdx.x;
    const int wid  = tid >> 5;
    const int lane = tid & 31;
    const int z     = blockIdx.z;
    const int mTile = blockIdx.y;
    const int nTile = blockIdx.x;

    const int m0 = (wid & 1) * 64;
    const int n0 = (wid >> 1) * 32;

    const size_t brA = (size_t)z * NPTS * K;
    const size_t brC = (size_t)z * NPTS * Ntot;
    const f16* gA  = A + brA + (size_t)mTile * 128 * K;
    const f16* gBh = Bh + (size_t)nTile * 128;
    const f16* gBl = BSPLIT ? Bl + (size_t)nTile * 128 : nullptr;

    float acc[4][4][4];
#pragma unroll
    for (int i = 0; i < 4; i++)
#pragma unroll
        for (int j = 0; j < 4; j++)
#pragma unroll
            for (int t = 0; t < 4; t++) acc[i][j][t] = 0.0f;

    const int nch = K >> 6;
#pragma unroll
    for (int s = 0; s < NSTAGE - 1; s++) {
        if (s < nch)
            issue_hg<BSPLIT>(gA, gBh, gBl, K, Ntot, s, sb0 + s * STAGE, tid);
        else
            cp_commit();
    }

    int bufn = (NSTAGE - 1) % NSTAGE;
    for (int c = 0; c < nch; c++) {
        if (c + NSTAGE - 1 < nch)
            issue_hg<BSPLIT>(gA, gBh, gBl, K, Ntot, c + NSTAGE - 1,
                             sb0 + bufn * STAGE, tid);
        else
            cp_commit();
        bufn = bufn == NSTAGE - 1 ? 0 : bufn + 1;
        cp_wait<NSTAGE - 1>();
        __syncthreads();

        const uint32_t sb = sb0 + (c % NSTAGE) * STAGE;
        const uint32_t sA = sb, sB = sb + 16384;

#pragma unroll
        for (int ks = 0; ks < 4; ks++) {
            uint32_t bh[4][2], bl[4][2];
#pragma unroll
            for (int pr = 0; pr < 2; pr++) {
                int k   = ks * 16 + (lane & 15);
                int chn = ((n0 + pr * 16) >> 3) + (lane >> 4);
                uint32_t ba = sB + (uint32_t)(k * 256 + ((chn ^ (k & 7)) << 4));
                uint32_t t[4];
                ldsm4t(t, ba);
                bh[pr * 2][0] = t[0]; bh[pr * 2][1] = t[1];
                bh[pr * 2 + 1][0] = t[2]; bh[pr * 2 + 1][1] = t[3];
                if (BSPLIT) {
                    ldsm4t(t, ba + 16384);
                    bl[pr * 2][0] = t[0]; bl[pr * 2][1] = t[1];
                    bl[pr * 2 + 1][0] = t[2]; bl[pr * 2 + 1][1] = t[3];
                }
            }
#pragma unroll
            for (int mf = 0; mf < 4; mf++) {
                int r   = m0 + mf * 16 + (lane & 15);
                int chk = ks * 2 + (lane >> 4);
                uint32_t aa = sA + (uint32_t)(r * 128 + ((chk ^ (r & 7)) << 4));
                uint32_t av[4];
                ldsm4(av, aa);
#pragma unroll
                for (int nf = 0; nf < 4; nf++) {
                    mma_hf(acc[mf][nf], av, bh[nf]);
                    if (BSPLIT) mma_hf(acc[mf][nf], av, bl[nf]);
                }
            }
        }
        __syncthreads();
    }

    const int g  = lane >> 2;
    const int tg = lane & 3;

    float ts[4][2], tq[4][2];
    if (OUT == 1) {
#pragma unroll
        for (int nf = 0; nf < 4; nf++)
            ts[nf][0] = ts[nf][1] = tq[nf][0] = tq[nf][1] = 0.0f;
    }

#pragma unroll
    for (int mf = 0; mf < 4; mf++) {
#pragma unroll
        for (int nf = 0; nf < 4; nf++) {
            int col = nTile * 128 + n0 + nf * 8 + tg * 2;
            float b0 = bias ? bias[col] : 0.0f;
            float b1 = bias ? bias[col + 1] : 0.0f;
#pragma unroll
            for (int hrow = 0; hrow < 2; hrow++) {
                int row = mTile * 128 + m0 + mf * 16 + g + hrow * 8;
                float v0 = acc[mf][nf][hrow * 2 + 0] + b0;
                float v1 = acc[mf][nf][hrow * 2 + 1] + b1;
                size_t o = brC + (size_t)row * Ntot + col;
                __half2 p = __floats2half2_rn(v0, v1);
                *reinterpret_cast<__half2*>(Cs + o) = p;
                if (OUT == 1) {
                    ts[nf][0] += v0;  tq[nf][0] = fmaf(v0, v0, tq[nf][0]);
                    ts[nf][1] += v1;  tq[nf][1] = fmaf(v1, v1, tq[nf][1]);
                }
            }
        }
    }

    if (OUT == 1) {
        float* st = stats + (size_t)z * 2 * COUT;
#pragma unroll
        for (int nf = 0; nf < 4; nf++) {
#pragma unroll
            for (int p = 0; p < 2; p++) {
#pragma unroll
                for (int off = 4; off <= 16; off <<= 1) {
                    ts[nf][p] += __shfl_xor_sync(0xFFFFFFFFu, ts[nf][p], off);
                    tq[nf][p] += __shfl_xor_sync(0xFFFFFFFFu, tq[nf][p], off);
                }
            }
        }
        if (lane < 4) {
#pragma unroll
            for (int nf = 0; nf < 4; nf++) {
                int col = nTile * 128 + n0 + nf * 8 + tg * 2;
                atomicAdd(&st[col],            ts[nf][0]);
                atomicAdd(&st[col + 1],        ts[nf][1]);
                atomicAdd(&st[COUT + col],     tq[nf][0]);
                atomicAdd(&st[COUT + col + 1], tq[nf][1]);
            }
        }
    }
}

// ---------------------------------------------------------------------------
// Conversions
// ---------------------------------------------------------------------------
__global__ void __launch_bounds__(256)
conv_act_f16(const float* __restrict__ a0, const float* __restrict__ a1,
             f16* __restrict__ o, int n4)
{
    const int z = blockIdx.y;
    const float* a = z ? a1 : a0;
    const size_t off = (size_t)z * n4;
    int i = blockIdx.x * 256 + threadIdx.x;
    if (i < n4) {
        float4 v = reinterpret_cast<const float4*>(a)[i];
        __half2 p0 = __floats2half2_rn(v.x, v.y);
        __half2 p1 = __floats2half2_rn(v.z, v.w);
        uint2 pk;
        pk.x = *reinterpret_cast<uint32_t*>(&p0);
        pk.y = *reinterpret_cast<uint32_t*>(&p1);
        reinterpret_cast<uint2*>(o)[off + i] = pk;
    }
}

__global__ void __launch_bounds__(256)
split_w_f16(const float* __restrict__ in, f16* __restrict__ oh, f16* __restrict__ ol, int n)
{
    int i = blockIdx.x * 256 + threadIdx.x;
    if (i < n) {
        float v = in[i];
        f16 h = __float2half(v);
        oh[i] = h;
        if (ol) ol[i] = __float2half(v - __half2float(h));
    }
}

// ---------------------------------------------------------------------------
// KPConv aggregation, f32x2 packed-FMA, 4 channels/thread, unroll-4 gathers.
// ---------------------------------------------------------------------------
__global__ void __launch_bounds__(128)
kpconv_agg4(const f16* __restrict__ hbuf,
            const float* __restrict__ coords0, const float* __restrict__ coords1,
            const int* __restrict__ neighb0, const int* __restrict__ neighb1,
            const float* __restrict__ kpts, f16* __restrict__ agg)
{
    const int z = blockIdx.z;
    const float* coords = z ? coords1 : coords0;
    const int*   neighb = z ? neighb1 : neighb0;
    const size_t brH = (size_t)z * NPTS * CMID;
    const size_t brA = (size_t)z * NPTS * PC;

    const int t   = threadIdx.x;
    const int pt  = t >> 5;
    const int u   = t & 31;
    const int n   = blockIdx.x * 4 + pt;

    __shared__ int   nb_s[4][KNB];
    __shared__ float rel_s[4][KNB][3];
    __shared__ __align__(8) ull ipack[4][KNB][16];

    nb_s[pt][u] = neighb[n * KNB + u];
    __syncthreads();
    for (int idx = u; idx < KNB * 3; idx += 32) {
        int k = idx / 3, d = idx % 3;
        rel_s[pt][k][d] = coords[(size_t)nb_s[pt][k] * 3 + d]
                        - coords[(size_t)n * 3 + d];
    }
    __syncthreads();
    for (int idx = u; idx < KNB * PKP; idx += 32) {
        int k = idx / PKP, p = idx % PKP;
        float dx = rel_s[pt][k][0] - kpts[p * 3 + 0];
        float dy = rel_s[pt][k][1] - kpts[p * 3 + 1];
        float dz = rel_s[pt][k][2] - kpts[p * 3 + 2];
        float d  = sqrtf(dx * dx + dy * dy + dz * dz);
        float iv = fmaxf(0.0f, 1.0f - d * 1.25f);   // EXTENT = 0.8
        ipack[pt][k][p] = pack2(iv, iv);
    }
    __syncthreads();

    ull acc2[PKP][2];
#pragma unroll
    for (int p = 0; p < PKP; p++) { acc2[p][0] = 0ull; acc2[p][1] = 0ull; }

#pragma unroll 4
    for (int k = 0; k < KNB; k++) {
        uint2 hv = __ldg(reinterpret_cast<const uint2*>(
            hbuf + brH + (size_t)nb_s[pt][k] * CMID + u * 4));
        __half2 h01 = *reinterpret_cast<__half2*>(&hv.x);
        __half2 h23 = *reinterpret_cast<__half2*>(&hv.y);
        float2 f01 = __half22float2(h01);
        float2 f23 = __half22float2(h23);
        ull av0 = pack2(f01.x, f01.y);
        ull av1 = pack2(f23.x, f23.y);
        const ull* ip = ipack[pt][k];
#pragma unroll
        for (int p = 0; p < PKP; p++) {
            ull iv = ip[p];
            fma2(acc2[p][0], av0, iv);
            fma2(acc2[p][1], av1, iv);
        }
    }

    f16* o = agg + brA + (size_t)n * PC + u * 4;
#pragma unroll
    for (int p = 0; p < PKP; p++) {
        float x0, y0, x1, y1;
        unpack2(acc2[p][0], x0, y0);
        unpack2(acc2[p][1], x1, y1);
        __half2 h01 = __floats2half2_rn(x0, y0);
        __half2 h23 = __floats2half2_rn(x1, y1);
        uint2 pk;
        pk.x = *reinterpret_cast<uint32_t*>(&h01);
        pk.y = *reinterpret_cast<uint32_t*>(&h23);
        *reinterpret_cast<uint2*>(o + (size_t)p * CMID) = pk;
    }
}

// ---------------------------------------------------------------------------
// BatchNorm apply (y fp16, stats fp32 from GEMM3 epilogue)
// ---------------------------------------------------------------------------
__global__ void zero_stats(float* s)
{
    s[blockIdx.x * 1024 + threadIdx.x] = 0.0f;   // <<<2, 1024>>>
}

__global__ void __launch_bounds__(256)
bn_apply4(const f16* __restrict__ ybase, const float* __restrict__ stats,
          const float* __restrict__ gamma, const float* __restrict__ beta,
          float* __restrict__ outbase)
{
    const int z = blockIdx.y;
    const f16*   y   = ybase + (size_t)z * NPTS * COUT;
    const float* st  = stats + (size_t)z * 2 * COUT;
    float*       out = outbase + (size_t)z * NPTS * COUT;

    const int i = blockIdx.x * blockDim.x + threadIdx.x;
    const int c = (i * 4) & (COUT - 1);
    uint2 pk = reinterpret_cast<const uint2*>(y)[i];
    __half2 h01 = *reinterpret_cast<__half2*>(&pk.x);
    __half2 h23 = *reinterpret_cast<__half2*>(&pk.y);
    float2 f01 = __half22float2(h01);
    float2 f23 = __half22float2(h23);
    float r[4] = {f01.x, f01.y, f23.x, f23.y};
#pragma unroll
    for (int j = 0; j < 4; j++) {
        float mu  = st[c + j] * (1.0f / NPTS);
        float var = st[COUT + c + j] * (1.0f / NPTS) - mu * mu;
        float scale = rsqrtf(var + 1e-5f) * gamma[c + j];
        float t = (r[j] - mu) * scale + beta[c + j];
        r[j] = (t >= 0.0f) ? t : 0.1f * t;
    }
    reinterpret_cast<float4*>(out)[i] = make_float4(r[0], r[1], r[2], r[3]);
}

__global__ void copy_coords(const float* __restrict__ a, const float* __restrict__ b,
                            float* __restrict__ out)
{
    int i = blockIdx.x * blockDim.x + threadIdx.x;
    if (i < NPTS * 3) {
        out[i]            = a[i];
        out[NPTS * 3 + i] = b[i];
    }
}

// ---------------------------------------------------------------------------
// Launcher — kpconv_agg4 is deliberately the 4th launch (ncu captures #4)
// ---------------------------------------------------------------------------
#define SMEM_SPLIT2  (2 * 49152)   // BSPLIT=1, 2 stages: 96 KB
#define SMEM_SINGLE3 (3 * 32768)   // BSPLIT=0, 3 stages: 96 KB

extern "C" void kernel_launch(void* const* d_in, const int* in_sizes, int n_in,
                              void* d_out, int out_size)
{
    (void)in_sizes; (void)n_in; (void)out_size;

    const float* src    = (const float*)d_in[0];
    const float* tgt    = (const float*)d_in[1];
    const float* sc     = (const float*)d_in[2];
    const float* tc     = (const float*)d_in[3];
    const int*   snb    = (const int*)  d_in[4];
    const int*   tnb    = (const int*)  d_in[5];
    const float* W_in   = (const float*)d_in[6];
    const float* b_in   = (const float*)d_in[7];
    const float* kpts   = (const float*)d_in[8];
    const float* kpw    = (const float*)d_in[9];
    const float* W_out  = (const float*)d_in[10];
    const float* b_out  = (const float*)d_in[11];
    const float* gamma  = (const float*)d_in[12];
    const float* beta   = (const float*)d_in[13];
    float* out = (float*)d_out;

    f16 *xs, *h, *ag, *md, *y16, *wi_h, *wi_l, *kw, *wo_h, *wo_l;
    float *stats;
    cudaGetSymbolAddress((void**)&xs,   g_xs);
    cudaGetSymbolAddress((void**)&h,    g_h);
    cudaGetSymbolAddress((void**)&ag,   g_ag);
    cudaGetSymbolAddress((void**)&md,   g_md);
    cudaGetSymbolAddress((void**)&y16,  g_y);
    cudaGetSymbolAddress((void**)&wi_h, g_wi_h);  cudaGetSymbolAddress((void**)&wi_l, g_wi_l);
    cudaGetSymbolAddress((void**)&kw,   g_kw);
    cudaGetSymbolAddress((void**)&wo_h, g_wo_h);  cudaGetSymbolAddress((void**)&wo_l, g_wo_l);
    cudaGetSymbolAddress((void**)&stats, g_stats);

    cudaFuncSetAttribute((const void*)hgemm<1, 0, 2>,
                         cudaFuncAttributeMaxDynamicSharedMemorySize, SMEM_SPLIT2);
    cudaFuncSetAttribute((const void*)hgemm<0, 0, 3>,
                         cudaFuncAttributeMaxDynamicSharedMemorySize, SMEM_SINGLE3);
    cudaFuncSetAttribute((const void*)hgemm<1, 1, 2>,
                         cudaFuncAttributeMaxDynamicSharedMemorySize, SMEM_SPLIT2);

    // --- launches 1-4 (ncu captures #4 = kpconv_agg4) ---
    split_w_f16<<<(CIN * CMID + 255) / 256, 256>>>(W_in, wi_h, wi_l, CIN * CMID);
    conv_act_f16<<<dim3((NPTS * CIN / 4 + 255) / 256, 2), 256>>>(
        src, tgt, xs, NPTS * CIN / 4);
    hgemm<1, 0, 2><<<dim3(1, NPTS / 128, 2), 256, SMEM_SPLIT2>>>(
        xs, wi_h, wi_l, b_in, h, nullptr, CIN, CMID);
    kpconv_agg4<<<dim3(NPTS / 4, 1, 2), 128>>>(h, sc, tc, snb, tnb, kpts, ag);

    // --- remaining preps + pipeline ---
    split_w_f16<<<(PC * CMID + 255) / 256, 256>>>(kpw, kw, nullptr, PC * CMID);
    split_w_f16<<<(CMID * COUT + 255) / 256, 256>>>(W_out, wo_h, wo_l, CMID * COUT);
    zero_stats<<<2, 1024>>>(stats);

    // mid = agg @ kpw (B single fp16) -> fp16
    hgemm<0, 0, 3><<<dim3(1, NPTS / 128, 2), 256, SMEM_SINGLE3>>>(
        ag, kw, nullptr, nullptr, md, nullptr, PC, CMID);

    // y = mid @ W_out + b_out (B split) -> fp16 + fused BN stats (fp32)
    hgemm<1, 1, 2><<<dim3(COUT / 128, NPTS / 128, 2), 256, SMEM_SPLIT2>>>(
        md, wo_h, wo_l, b_out, y16, stats, CMID, COUT);

    // BN normalize + LeakyReLU
    bn_apply4<<<dim3((NPTS * COUT / 4) / 256, 2), 256>>>(y16, stats, gamma, beta, out);

    // coords pass-through
    copy_coords<<<(NPTS * 3 + 255) / 256, 256>>>(sc, tc, out + 2ull * NPTS * COUT);
}

// round 14
// speedup vs baseline: 1.0764x; 1.0002x over previous
#include <cuda_runtime.h>
#include <cuda_fp16.h>
#include <math.h>
#include <stdint.h>

#define NPTS 16384
#define KNB  32
#define PKP  15
#define CIN  256
#define CMID 128
#define COUT 512
#define PC   (PKP * CMID)   // 1920

typedef unsigned long long ull;
typedef __half f16;

// ---------------------------------------------------------------------------
// Scratch (device globals -- allocation-free)
// ---------------------------------------------------------------------------
__device__ __align__(128) f16   g_xs  [2ull * NPTS * CIN];
__device__ __align__(128) f16   g_h   [2ull * NPTS * CMID];
__device__ __align__(128) f16   g_ag  [2ull * NPTS * PC];
__device__ __align__(128) f16   g_md  [2ull * NPTS * CMID];
__device__ __align__(128) f16   g_y   [2ull * NPTS * COUT];
__device__ __align__(128) f16   g_wi_h[CIN * CMID],  g_wi_l[CIN * CMID];
__device__ __align__(128) f16   g_kw  [PC * CMID];
__device__ __align__(128) f16   g_wo_h[CMID * COUT], g_wo_l[CMID * COUT];
__device__ float g_stats[2 * 2 * COUT];

// ---------------------------------------------------------------------------
// PTX helpers
// ---------------------------------------------------------------------------
__device__ __forceinline__ uint32_t s2u(const void* p)
{
    return (uint32_t)__cvta_generic_to_shared(p);
}
__device__ __forceinline__ void cpa16(uint32_t s, const void* g)
{
    asm volatile("cp.async.cg.shared.global [%0], [%1], 16;" :: "r"(s), "l"(g));
}
__device__ __forceinline__ void cp_commit()
{
    asm volatile("cp.async.commit_group;" ::: "memory");
}
template <int N>
__device__ __forceinline__ void cp_wait()
{
    asm volatile("cp.async.wait_group %0;" :: "n"(N) : "memory");
}
__device__ __forceinline__ void ldsm4(uint32_t* r, uint32_t a)
{
    asm volatile("ldmatrix.sync.aligned.m8n8.x4.shared.b16 {%0,%1,%2,%3}, [%4];"
                 : "=r"(r[0]), "=r"(r[1]), "=r"(r[2]), "=r"(r[3]) : "r"(a));
}
__device__ __forceinline__ void ldsm4t(uint32_t* r, uint32_t a)
{
    asm volatile("ldmatrix.sync.aligned.m8n8.x4.trans.shared.b16 {%0,%1,%2,%3}, [%4];"
                 : "=r"(r[0]), "=r"(r[1]), "=r"(r[2]), "=r"(r[3]) : "r"(a));
}
__device__ __forceinline__ void mma_hf(float* c, const uint32_t* a, const uint32_t* b)
{
    asm volatile(
        "mma.sync.aligned.m16n8k16.row.col.f32.f16.f16.f32 "
        "{%0,%1,%2,%3}, {%4,%5,%6,%7}, {%8,%9}, {%0,%1,%2,%3};"
        : "+f"(c[0]), "+f"(c[1]), "+f"(c[2]), "+f"(c[3])
        : "r"(a[0]), "r"(a[1]), "r"(a[2]), "r"(a[3]), "r"(b[0]), "r"(b[1]));
}
__device__ __forceinline__ void fma2(ull& d, ull a, ull b)
{
    asm("fma.rn.f32x2 %0, %1, %2, %0;" : "+l"(d) : "l"(a), "l"(b));
}
__device__ __forceinline__ ull pack2(float x, float y)
{
    ull r;
    asm("mov.b64 %0, {%1, %2};" : "=l"(r) : "f"(x), "f"(y));
    return r;
}
__device__ __forceinline__ void unpack2(ull v, float& x, float& y)
{
    asm("mov.b64 {%0, %1}, %2;" : "=f"(x), "=f"(y) : "l"(v));
}

// ---------------------------------------------------------------------------
// Unified fp16 HMMA GEMM, templated pipeline depth.
// A fp16 single; B fp16 single (BSPLIT=0) or hi/lo split (BSPLIT=1, 2 MMAs).
// CTA tile 128x128, BK=64, 8 warps (2m x 4n), warp tile 64x32.
// Stage: A[16K] + B[16K or 32K]; NSTAGE stages (<=96KB total => 2 CTAs/SM).
// OUT 0: fp16 out (+bias). OUT 1: fp16 out (+bias) + fp32 BN stats.
// ---------------------------------------------------------------------------
template <int BSPLIT>
__device__ __forceinline__ void issue_hg(
    const f16* gA, const f16* gBh, const f16* gBl,
    int K, int Ntot, int c, uint32_t sb, int tid)
{
    const int kt = c * 64;
#pragma unroll
    for (int i = 0; i < 4; i++) {
        int idx = tid + i * 256;            // A: 128 rows x 8 16B-chunks
        int r = idx >> 3, ch = idx & 7;
        uint32_t off = (uint32_t)(r * 128 + ((ch ^ (r & 7)) << 4));
        cpa16(sb + off, gA + (size_t)r * K + kt + ch * 8);
    }
#pragma unroll
    for (int i = 0; i < 4; i++) {
        int idx = tid + i * 256;            // B: 64 rows x 16 16B-chunks
        int r = idx >> 4, ch = idx & 15;
        uint32_t off = (uint32_t)(r * 256 + ((ch ^ (r & 7)) << 4));
        size_t go = (size_t)(kt + r) * Ntot + ch * 8;
        cpa16(sb + 16384 + off, gBh + go);
        if (BSPLIT) cpa16(sb + 32768 + off, gBl + go);
    }
    cp_commit();
}

template <int BSPLIT, int OUT, int NSTAGE>
__global__ void __launch_bounds__(256)
hgemm(const f16* __restrict__ A, const f16* __restrict__ Bh,
      const f16* __restrict__ Bl, const float* __restrict__ bias,
      f16* __restrict__ Cs, float* __restrict__ stats,
      int K, int Ntot)
{
    constexpr int STAGE = 16384 + (BSPLIT ? 32768 : 16384);
    extern __shared__ char smem[];
    const uint32_t sb0 = s2u(smem);

    const int tid  = threadIdx.x;
    const int wid  = tid >> 5;
    const int lane = tid & 31;
    const int z     = blockIdx.z;
    const int mTile = blockIdx.y;
    const int nTile = blockIdx.x;

    const int m0 = (wid & 1) * 64;
    const int n0 = (wid >> 1) * 32;

    const size_t brA = (size_t)z * NPTS * K;
    const size_t brC = (size_t)z * NPTS * Ntot;
    const f16* gA  = A + brA + (size_t)mTile * 128 * K;
    const f16* gBh = Bh + (size_t)nTile * 128;
    const f16* gBl = BSPLIT ? Bl + (size_t)nTile * 128 : nullptr;

    float acc[4][4][4];
#pragma unroll
    for (int i = 0; i < 4; i++)
#pragma unroll
        for (int j = 0; j < 4; j++)
#pragma unroll
            for (int t = 0; t < 4; t++) acc[i][j][t] = 0.0f;

    const int nch = K >> 6;
#pragma unroll
    for (int s = 0; s < NSTAGE - 1; s++) {
        if (s < nch)
            issue_hg<BSPLIT>(gA, gBh, gBl, K, Ntot, s, sb0 + s * STAGE, tid);
        else
            cp_commit();
    }

    int bufn = (NSTAGE - 1) % NSTAGE;
    for (int c = 0; c < nch; c++) {
        if (c + NSTAGE - 1 < nch)
            issue_hg<BSPLIT>(gA, gBh, gBl, K, Ntot, c + NSTAGE - 1,
                             sb0 + bufn * STAGE, tid);
        else
            cp_commit();
        bufn = bufn == NSTAGE - 1 ? 0 : bufn + 1;
        cp_wait<NSTAGE - 1>();
        __syncthreads();

        const uint32_t sb = sb0 + (c % NSTAGE) * STAGE;
        const uint32_t sA = sb, sB = sb + 16384;

#pragma unroll
        for (int ks = 0; ks < 4; ks++) {
            uint32_t bh[4][2], bl[4][2];
#pragma unroll
            for (int pr = 0; pr < 2; pr++) {
                int k   = ks * 16 + (lane & 15);
                int chn = ((n0 + pr * 16) >> 3) + (lane >> 4);
                uint32_t ba = sB + (uint32_t)(k * 256 + ((chn ^ (k & 7)) << 4));
                uint32_t t[4];
                ldsm4t(t, ba);
                bh[pr * 2][0] = t[0]; bh[pr * 2][1] = t[1];
                bh[pr * 2 + 1][0] = t[2]; bh[pr * 2 + 1][1] = t[3];
                if (BSPLIT) {
                    ldsm4t(t, ba + 16384);
                    bl[pr * 2][0] = t[0]; bl[pr * 2][1] = t[1];
                    bl[pr * 2 + 1][0] = t[2]; bl[pr * 2 + 1][1] = t[3];
                }
            }
#pragma unroll
            for (int mf = 0; mf < 4; mf++) {
                int r   = m0 + mf * 16 + (lane & 15);
                int chk = ks * 2 + (lane >> 4);
                uint32_t aa = sA + (uint32_t)(r * 128 + ((chk ^ (r & 7)) << 4));
                uint32_t av[4];
                ldsm4(av, aa);
#pragma unroll
                for (int nf = 0; nf < 4; nf++) {
                    mma_hf(acc[mf][nf], av, bh[nf]);
                    if (BSPLIT) mma_hf(acc[mf][nf], av, bl[nf]);
                }
            }
        }
        __syncthreads();
    }

    const int g  = lane >> 2;
    const int tg = lane & 3;

    float ts[4][2], tq[4][2];
    if (OUT == 1) {
#pragma unroll
        for (int nf = 0; nf < 4; nf++)
            ts[nf][0] = ts[nf][1] = tq[nf][0] = tq[nf][1] = 0.0f;
    }

#pragma unroll
    for (int mf = 0; mf < 4; mf++) {
#pragma unroll
        for (int nf = 0; nf < 4; nf++) {
            int col = nTile * 128 + n0 + nf * 8 + tg * 2;
            float b0 = bias ? bias[col] : 0.0f;
            float b1 = bias ? bias[col + 1] : 0.0f;
#pragma unroll
            for (int hrow = 0; hrow < 2; hrow++) {
                int row = mTile * 128 + m0 + mf * 16 + g + hrow * 8;
                float v0 = acc[mf][nf][hrow * 2 + 0] + b0;
                float v1 = acc[mf][nf][hrow * 2 + 1] + b1;
                size_t o = brC + (size_t)row * Ntot + col;
                __half2 p = __floats2half2_rn(v0, v1);
                *reinterpret_cast<__half2*>(Cs + o) = p;
                if (OUT == 1) {
                    ts[nf][0] += v0;  tq[nf][0] = fmaf(v0, v0, tq[nf][0]);
                    ts[nf][1] += v1;  tq[nf][1] = fmaf(v1, v1, tq[nf][1]);
                }
            }
        }
    }

    if (OUT == 1) {
        float* st = stats + (size_t)z * 2 * COUT;
#pragma unroll
        for (int nf = 0; nf < 4; nf++) {
#pragma unroll
            for (int p = 0; p < 2; p++) {
#pragma unroll
                for (int off = 4; off <= 16; off <<= 1) {
                    ts[nf][p] += __shfl_xor_sync(0xFFFFFFFFu, ts[nf][p], off);
                    tq[nf][p] += __shfl_xor_sync(0xFFFFFFFFu, tq[nf][p], off);
                }
            }
        }
        if (lane < 4) {
#pragma unroll
            for (int nf = 0; nf < 4; nf++) {
                int col = nTile * 128 + n0 + nf * 8 + tg * 2;
                atomicAdd(&st[col],            ts[nf][0]);
                atomicAdd(&st[col + 1],        ts[nf][1]);
                atomicAdd(&st[COUT + col],     tq[nf][0]);
                atomicAdd(&st[COUT + col + 1], tq[nf][1]);
            }
        }
    }
}

// ---------------------------------------------------------------------------
// Conversions
// ---------------------------------------------------------------------------
__global__ void __launch_bounds__(256)
conv_act_f16(const float* __restrict__ a0, const float* __restrict__ a1,
             f16* __restrict__ o, int n4)
{
    const int z = blockIdx.y;
    const float* a = z ? a1 : a0;
    const size_t off = (size_t)z * n4;
    int i = blockIdx.x * 256 + threadIdx.x;
    if (i < n4) {
        float4 v = reinterpret_cast<const float4*>(a)[i];
        __half2 p0 = __floats2half2_rn(v.x, v.y);
        __half2 p1 = __floats2half2_rn(v.z, v.w);
        uint2 pk;
        pk.x = *reinterpret_cast<uint32_t*>(&p0);
        pk.y = *reinterpret_cast<uint32_t*>(&p1);
        reinterpret_cast<uint2*>(o)[off + i] = pk;
    }
}

__global__ void __launch_bounds__(256)
split_w_f16(const float* __restrict__ in, f16* __restrict__ oh, f16* __restrict__ ol, int n)
{
    int i = blockIdx.x * 256 + threadIdx.x;
    if (i < n) {
        float v = in[i];
        f16 h = __float2half(v);
        oh[i] = h;
        if (ol) ol[i] = __float2half(v - __half2float(h));
    }
}

// ---------------------------------------------------------------------------
// KPConv aggregation, f32x2 packed-FMA, 4 channels/thread, unroll-4 gathers.
// ---------------------------------------------------------------------------
__global__ void __launch_bounds__(128)
kpconv_agg4(const f16* __restrict__ hbuf,
            const float* __restrict__ coords0, const float* __restrict__ coords1,
            const int* __restrict__ neighb0, const int* __restrict__ neighb1,
            const float* __restrict__ kpts, f16* __restrict__ agg)
{
    const int z = blockIdx.z;
    const float* coords = z ? coords1 : coords0;
    const int*   neighb = z ? neighb1 : neighb0;
    const size_t brH = (size_t)z * NPTS * CMID;
    const size_t brA = (size_t)z * NPTS * PC;

    const int t   = threadIdx.x;
    const int pt  = t >> 5;
    const int u   = t & 31;
    const int n   = blockIdx.x * 4 + pt;

    __shared__ int   nb_s[4][KNB];
    __shared__ float rel_s[4][KNB][3];
    __shared__ __align__(8) ull ipack[4][KNB][16];

    nb_s[pt][u] = neighb[n * KNB + u];
    __syncthreads();
    for (int idx = u; idx < KNB * 3; idx += 32) {
        int k = idx / 3, d = idx % 3;
        rel_s[pt][k][d] = coords[(size_t)nb_s[pt][k] * 3 + d]
                        - coords[(size_t)n * 3 + d];
    }
    __syncthreads();
    for (int idx = u; idx < KNB * PKP; idx += 32) {
        int k = idx / PKP, p = idx % PKP;
        float dx = rel_s[pt][k][0] - kpts[p * 3 + 0];
        float dy = rel_s[pt][k][1] - kpts[p * 3 + 1];
        float dz = rel_s[pt][k][2] - kpts[p * 3 + 2];
        float d  = sqrtf(dx * dx + dy * dy + dz * dz);
        float iv = fmaxf(0.0f, 1.0f - d * 1.25f);   // EXTENT = 0.8
        ipack[pt][k][p] = pack2(iv, iv);
    }
    __syncthreads();

    ull acc2[PKP][2];
#pragma unroll
    for (int p = 0; p < PKP; p++) { acc2[p][0] = 0ull; acc2[p][1] = 0ull; }

#pragma unroll 4
    for (int k = 0; k < KNB; k++) {
        uint2 hv = __ldg(reinterpret_cast<const uint2*>(
            hbuf + brH + (size_t)nb_s[pt][k] * CMID + u * 4));
        __half2 h01 = *reinterpret_cast<__half2*>(&hv.x);
        __half2 h23 = *reinterpret_cast<__half2*>(&hv.y);
        float2 f01 = __half22float2(h01);
        float2 f23 = __half22float2(h23);
        ull av0 = pack2(f01.x, f01.y);
        ull av1 = pack2(f23.x, f23.y);
        const ull* ip = ipack[pt][k];
#pragma unroll
        for (int p = 0; p < PKP; p++) {
            ull iv = ip[p];
            fma2(acc2[p][0], av0, iv);
            fma2(acc2[p][1], av1, iv);
        }
    }

    f16* o = agg + brA + (size_t)n * PC + u * 4;
#pragma unroll
    for (int p = 0; p < PKP; p++) {
        float x0, y0, x1, y1;
        unpack2(acc2[p][0], x0, y0);
        unpack2(acc2[p][1], x1, y1);
        __half2 h01 = __floats2half2_rn(x0, y0);
        __half2 h23 = __floats2half2_rn(x1, y1);
        uint2 pk;
        pk.x = *reinterpret_cast<uint32_t*>(&h01);
        pk.y = *reinterpret_cast<uint32_t*>(&h23);
        *reinterpret_cast<uint2*>(o + (size_t)p * CMID) = pk;
    }
}

// ---------------------------------------------------------------------------
// BatchNorm apply (y fp16, stats fp32 from GEMM3 epilogue)
// ---------------------------------------------------------------------------
__global__ void zero_stats(float* s)
{
    s[blockIdx.x * 1024 + threadIdx.x] = 0.0f;   // <<<2, 1024>>>
}

__global__ void __launch_bounds__(256)
bn_apply4(const f16* __restrict__ ybase, const float* __restrict__ stats,
          const float* __restrict__ gamma, const float* __restrict__ beta,
          float* __restrict__ outbase)
{
    const int z = blockIdx.y;
    const f16*   y   = ybase + (size_t)z * NPTS * COUT;
    const float* st  = stats + (size_t)z * 2 * COUT;
    float*       out = outbase + (size_t)z * NPTS * COUT;

    const int i = blockIdx.x * blockDim.x + threadIdx.x;
    const int c = (i * 4) & (COUT - 1);
    uint2 pk = reinterpret_cast<const uint2*>(y)[i];
    __half2 h01 = *reinterpret_cast<__half2*>(&pk.x);
    __half2 h23 = *reinterpret_cast<__half2*>(&pk.y);
    float2 f01 = __half22float2(h01);
    float2 f23 = __half22float2(h23);
    float r[4] = {f01.x, f01.y, f23.x, f23.y};
#pragma unroll
    for (int j = 0; j < 4; j++) {
        float mu  = st[c + j] * (1.0f / NPTS);
        float var = st[COUT + c + j] * (1.0f / NPTS) - mu * mu;
        float scale = rsqrtf(var + 1e-5f) * gamma[c + j];
        float t = (r[j] - mu) * scale + beta[c + j];
        r[j] = (t >= 0.0f) ? t : 0.1f * t;
    }
    reinterpret_cast<float4*>(out)[i] = make_float4(r[0], r[1], r[2], r[3]);
}

__global__ void copy_coords(const float* __restrict__ a, const float* __restrict__ b,
                            float* __restrict__ out)
{
    int i = blockIdx.x * blockDim.x + threadIdx.x;
    if (i < NPTS * 3) {
        out[i]            = a[i];
        out[NPTS * 3 + i] = b[i];
    }
}

// ---------------------------------------------------------------------------
// Launcher — kpconv_agg4 is deliberately the 4th launch (ncu captures #4)
// ---------------------------------------------------------------------------
#define SMEM_SPLIT2  (2 * 49152)   // BSPLIT=1, 2 stages: 96 KB
#define SMEM_SINGLE3 (3 * 32768)   // BSPLIT=0, 3 stages: 96 KB

extern "C" void kernel_launch(void* const* d_in, const int* in_sizes, int n_in,
                              void* d_out, int out_size)
{
    (void)in_sizes; (void)n_in; (void)out_size;

    const float* src    = (const float*)d_in[0];
    const float* tgt    = (const float*)d_in[1];
    const float* sc     = (const float*)d_in[2];
    const float* tc     = (const float*)d_in[3];
    const int*   snb    = (const int*)  d_in[4];
    const int*   tnb    = (const int*)  d_in[5];
    const float* W_in   = (const float*)d_in[6];
    const float* b_in   = (const float*)d_in[7];
    const float* kpts   = (const float*)d_in[8];
    const float* kpw    = (const float*)d_in[9];
    const float* W_out  = (const float*)d_in[10];
    const float* b_out  = (const float*)d_in[11];
    const float* gamma  = (const float*)d_in[12];
    const float* beta   = (const float*)d_in[13];
    float* out = (float*)d_out;

    f16 *xs, *h, *ag, *md, *y16, *wi_h, *wi_l, *kw, *wo_h, *wo_l;
    float *stats;
    cudaGetSymbolAddress((void**)&xs,   g_xs);
    cudaGetSymbolAddress((void**)&h,    g_h);
    cudaGetSymbolAddress((void**)&ag,   g_ag);
    cudaGetSymbolAddress((void**)&md,   g_md);
    cudaGetSymbolAddress((void**)&y16,  g_y);
    cudaGetSymbolAddress((void**)&wi_h, g_wi_h);  cudaGetSymbolAddress((void**)&wi_l, g_wi_l);
    cudaGetSymbolAddress((void**)&kw,   g_kw);
    cudaGetSymbolAddress((void**)&wo_h, g_wo_h);  cudaGetSymbolAddress((void**)&wo_l, g_wo_l);
    cudaGetSymbolAddress((void**)&stats, g_stats);

    cudaFuncSetAttribute((const void*)hgemm<1, 0, 2>,
                         cudaFuncAttributeMaxDynamicSharedMemorySize, SMEM_SPLIT2);
    cudaFuncSetAttribute((const void*)hgemm<0, 0, 3>,
                         cudaFuncAttributeMaxDynamicSharedMemorySize, SMEM_SINGLE3);
    cudaFuncSetAttribute((const void*)hgemm<1, 1, 2>,
                         cudaFuncAttributeMaxDynamicSharedMemorySize, SMEM_SPLIT2);

    // --- launches 1-4 (ncu captures #4 = kpconv_agg4) ---
    split_w_f16<<<(CIN * CMID + 255) / 256, 256>>>(W_in, wi_h, wi_l, CIN * CMID);
    conv_act_f16<<<dim3((NPTS * CIN / 4 + 255) / 256, 2), 256>>>(
        src, tgt, xs, NPTS * CIN / 4);
    hgemm<1, 0, 2><<<dim3(1, NPTS / 128, 2), 256, SMEM_SPLIT2>>>(
        xs, wi_h, wi_l, b_in, h, nullptr, CIN, CMID);
    kpconv_agg4<<<dim3(NPTS / 4, 1, 2), 128>>>(h, sc, tc, snb, tnb, kpts, ag);

    // --- remaining preps + pipeline ---
    split_w_f16<<<(PC * CMID + 255) / 256, 256>>>(kpw, kw, nullptr, PC * CMID);
    split_w_f16<<<(CMID * COUT + 255) / 256, 256>>>(W_out, wo_h, wo_l, CMID * COUT);
    zero_stats<<<2, 1024>>>(stats);

    // mid = agg @ kpw (B single fp16) -> fp16
    hgemm<0, 0, 3><<<dim3(1, NPTS / 128, 2), 256, SMEM_SINGLE3>>>(
        ag, kw, nullptr, nullptr, md, nullptr, PC, CMID);

    // y = mid @ W_out + b_out (B split) -> fp16 + fused BN stats (fp32)
    hgemm<1, 1, 2><<<dim3(COUT / 128, NPTS / 128, 2), 256, SMEM_SPLIT2>>>(
        md, wo_h, wo_l, b_out, y16, stats, CMID, COUT);

    // BN normalize + LeakyReLU
    bn_apply4<<<dim3((NPTS * COUT / 4) / 256, 2), 256>>>(y16, stats, gamma, beta, out);

    // coords pass-through
    copy_coords<<<(NPTS * 3 + 255) / 256, 256>>>(sc, tc, out + 2ull * NPTS * COUT);
}